// round 14
// baseline (speedup 1.0000x reference)
#include <cuda_runtime.h>
#include <cstdint>
#include <cstddef>

#define MAXN      262144
#define HBITS     19
#define HSIZE     (1u<<HBITS)
#define HMASK     (HSIZE-1u)
#define CH_BITS   14
#define CH_SIZE   (1u<<CH_BITS)
#define CH_MASK   (CH_SIZE-1u)
#define HIST_SIZE 262144
#define CAND_CAP  4096
#define LF        96
#define DF        32
#define TOPK      128
#define BPTS      256

typedef unsigned long long u64;

// ---------------- static scratch ---------------------------------------------
__device__ u64   g_h2[HSIZE];          // insert: (key<<18)|minIdx ; scored: (key<<32)|scoreBits
__device__ u64   g_cell[CH_SIZE];      // (key<<16)|(k<<5)|o ; ~0 = empty
__device__ u64   g_comp[MAXN];         // peak composite keys (0 = not peak)
__device__ int   g_hist[HIST_SIZE];    // histogram of PEAK scores (sb>>12)
__device__ u64   g_cand[CAND_CAP];
__device__ int   g_cnt3[4];            // [1]=cand count [2]=thresh bucket
__device__ int   g_widx[TOPK];
__device__ float g_wconf[TOPK];
__device__ float g_pool[(size_t)TOPK*27*LF];
__device__ int   g_cellpts[TOPK*27];
__device__ float g_cdesc[129*DF];
__device__ float g_H[(size_t)MAXN*DF];

// batch-blind 30-bit key (reference int32 overflow kills the batch term;
// coord fields always in (0,1024) so 10-bit packing is injective like ref)
__device__ __forceinline__ unsigned enc3(int x, int y, int z) {
    return ((unsigned)(x + 512) << 20) | ((unsigned)(y + 512) << 10)
         |  (unsigned)(z + 512);
}
__device__ __forceinline__ unsigned h19(unsigned k) { return (k * 2654435769u) >> 13; }
__device__ __forceinline__ unsigned h14(unsigned k) { return (k * 2654435769u) >> 18; }

__device__ __forceinline__ u64 pack2(float lo, float hi) {
    u64 r; asm("mov.b64 %0, {%1, %2};" : "=l"(r) : "f"(lo), "f"(hi)); return r;
}
__device__ __forceinline__ void unpack2(u64 v, float& lo, float& hi) {
    asm("mov.b64 {%0, %1}, %2;" : "=f"(lo), "=f"(hi) : "l"(v));
}
__device__ __forceinline__ u64 fma2(u64 a, u64 b, u64 c) {
    u64 r; asm("fma.rn.f32x2 %0, %1, %2, %3;" : "=l"(r) : "l"(a), "l"(b), "l"(c)); return r;
}

// ---------------- fused init --------------------------------------------------
__global__ void k_init() {
    int i = blockIdx.x * blockDim.x + threadIdx.x;           // 524288 threads
    if (i < (int)HSIZE)      g_h2[i] = ~0ull;
    if (i < (int)CH_SIZE)    g_cell[i] = ~0ull;
    if (i < HIST_SIZE)       g_hist[i] = 0;
    if (i < TOPK*27)         g_cellpts[i] = 0;
    if (i < TOPK*27*LF)      g_pool[i] = 0.0f;
    if (i < 4)               g_cnt3[i] = 0;
}

// ---------------- h2 insert: per-cell min index over masked points -----------
__global__ void k_h2_insert(const int* __restrict__ coords, const float* __restrict__ scores, int N) {
    int i = blockIdx.x * blockDim.x + threadIdx.x;
    if (i >= N) return;
    if (!(scores[i] > 0.1f)) return;
    int4 c = ((const int4*)coords)[i];
    unsigned key = enc3(c.y, c.z, c.w);
    u64 w = ((u64)key << 18) | (unsigned)i;
    unsigned s = h19(key);
    for (;;) {
        u64 cur = g_h2[s];
        if (cur == ~0ull) {
            u64 old = atomicCAS(&g_h2[s], ~0ull, w);
            if (old == ~0ull) return;
            cur = old;
        }
        if ((unsigned)(cur >> 18) == key) { atomicMin(&g_h2[s], w); return; }
        s = (s + 1) & HMASK;
    }
}

// rewrite occupied slots to (key<<32)|scoreBits: one load per tap in k_peaks
__global__ void k_h2_score(const float* __restrict__ scores) {
    int s = blockIdx.x * blockDim.x + threadIdx.x;
    if (s >= (int)HSIZE) return;
    u64 cur = g_h2[s];
    if (cur == ~0ull) return;
    unsigned idx = (unsigned)(cur & 0x3FFFFu);
    unsigned key = (unsigned)(cur >> 18);
    g_h2[s] = ((u64)key << 32) | __float_as_uint(scores[idx]);
}

// ---------------- peaks: 27-tap max, 9-way MLP-batched probes ----------------
__global__ void k_peaks(const int* __restrict__ coords, const float* __restrict__ scores, int N) {
    int i = blockIdx.x * blockDim.x + threadIdx.x;
    if (i >= N) return;
    float sc = scores[i];
    if (!(sc > 0.1f)) { g_comp[i] = 0ull; return; }
    int4 c = ((const int4*)coords)[i];
    unsigned key = enc3(c.y, c.z, c.w);
    float hmax = -1.0f;
    #pragma unroll
    for (int g = 0; g < 3; g++) {                       // dx = g-1 plane
        unsigned kbase = key + ((unsigned)(g - 1) << 20);
        u64 cur[9]; unsigned slot[9];
        #pragma unroll
        for (int o = 0; o < 9; o++) {                   // phase 1: 9 independent loads
            int dy = o/3 - 1, dz = o%3 - 1;
            unsigned nk = kbase + ((unsigned)dy << 10) + (unsigned)dz;
            slot[o] = h19(nk);
            cur[o] = g_h2[slot[o]];
        }
        #pragma unroll
        for (int o = 0; o < 9; o++) {                   // phase 2: resolve (rare probing)
            int dy = o/3 - 1, dz = o%3 - 1;
            unsigned nk = kbase + ((unsigned)dy << 10) + (unsigned)dz;
            u64 cu = cur[o]; unsigned s = slot[o];
            while (cu != ~0ull && (unsigned)(cu >> 32) != nk) {
                s = (s + 1) & HMASK;
                cu = g_h2[s];
            }
            if (cu != ~0ull) hmax = fmaxf(hmax, __uint_as_float((unsigned)cu));
        }
    }
    if (hmax == sc) {
        unsigned sb = __float_as_uint(sc);
        g_comp[i] = ((u64)sb << 32) | (u64)(0xFFFFFFFFu - (unsigned)i);
        atomicAdd(&g_hist[sb >> 12], 1);
    } else {
        g_comp[i] = 0ull;
    }
}

// scores < 1.0 => max useful bucket 260095 => first chunk base:
#define THRESH_BASE0 ((260095/1024)*1024)

// parallel suffix-scan threshold: largest bucket T with #peaks(>=T) >= TOPK
__global__ void k_thresh() {
    __shared__ int sh[1024];
    __shared__ int cumsh;
    int t = threadIdx.x;
    if (t == 0) cumsh = 0;
    __syncthreads();
    for (int base = THRESH_BASE0; base >= 0; base -= 1024) {
        sh[t] = g_hist[base + t];
        __syncthreads();
        #pragma unroll
        for (int off = 1; off < 1024; off <<= 1) {      // suffix sum (Hillis-Steele)
            int add = (t + off < 1024) ? sh[t + off] : 0;
            __syncthreads();
            sh[t] += add;
            __syncthreads();
        }
        int cum0 = cumsh;
        int total = sh[0];
        if (cum0 + total >= TOPK) {
            bool cond  = (cum0 + sh[t]) >= TOPK;        // monotone in t
            bool condn = (t < 1023) && ((cum0 + sh[t + 1]) >= TOPK);
            if (cond && !condn) g_cnt3[2] = base + t;
            return;
        }
        __syncthreads();
        if (t == 0) cumsh = cum0 + total;
        __syncthreads();
    }
}

__global__ void k_collect(int N) {
    int i = blockIdx.x * blockDim.x + threadIdx.x;
    if (i >= N) return;
    u64 c = g_comp[i];
    if (c == 0ull) return;
    if ((int)(c >> 44) >= g_cnt3[2]) {
        int p = atomicAdd(&g_cnt3[1], 1);
        if (p < CAND_CAP) g_cand[p] = c;
    }
}

// bitonic sort (desc), emit top-128 + conf, then build winner-cell hash
__global__ void k_select(float* __restrict__ conf_out,
                         const int* __restrict__ coords, const float* __restrict__ offs) {
    __shared__ u64 s[CAND_CAP];
    int t = threadIdx.x; // 1024
    int n = g_cnt3[1]; if (n > CAND_CAP) n = CAND_CAP;
    int M = TOPK; while (M < n) M <<= 1;
    for (int i = t; i < M; i += 1024) s[i] = (i < n) ? g_cand[i] : 0ull;
    __syncthreads();
    for (int k = 2; k <= M; k <<= 1) {
        for (int j = k >> 1; j > 0; j >>= 1) {
            for (int i = t; i < M; i += 1024) {
                int l = i ^ j;
                if (l > i) {
                    u64 a = s[i], b = s[l];
                    bool up = ((i & k) == 0);
                    if (up ? (a < b) : (a > b)) { s[i] = b; s[l] = a; }
                }
            }
            __syncthreads();
        }
    }
    if (t < TOPK) {
        u64 c = s[t];
        int widx = -1;
        if (c != 0ull) {
            float sc = __uint_as_float((unsigned)(c >> 32));
            g_wconf[t] = sc;
            widx = (int)(0xFFFFFFFFu - (unsigned)(c & 0xFFFFFFFFull));
            g_widx[t] = widx;
            conf_out[t] = sc;
        } else {
            g_wconf[t] = 0.0f; g_widx[t] = -1; conf_out[t] = 0.0f;
        }
        if (widx >= 0) {
            int cx = coords[4*widx+1] + (int)offs[3*widx];
            int cy = coords[4*widx+2] + (int)offs[3*widx+1];
            int cz = coords[4*widx+3] + (int)offs[3*widx+2];
            for (int o = 0; o < 27; o++) {
                int dx = o/9 - 1, dy = (o/3)%3 - 1, dz = o%3 - 1;
                unsigned key = enc3(cx+dx, cy+dy, cz+dz);
                u64 w = ((u64)key << 16) | (unsigned)((t << 5) | o);
                unsigned h = h14(key);
                for (;;) {
                    u64 old = atomicCAS(&g_cell[h], ~0ull, w);
                    if (old == ~0ull) break;
                    h = (h + 1) & CH_MASK;
                }
            }
        }
    }
}

// ---------------- point pass: one hash probe per point -----------------------
__global__ void k_match(const int* __restrict__ coords, const float* __restrict__ offs,
                        const float* __restrict__ feats, int N) {
    int i = blockIdx.x * blockDim.x + threadIdx.x;
    if (i >= N) return;
    int4 c = ((const int4*)coords)[i];
    int nx = c.y + (int)offs[3*i];
    int ny = c.z + (int)offs[3*i+1];
    int nz = c.w + (int)offs[3*i+2];
    unsigned key = enc3(nx, ny, nz);
    unsigned s = h14(key);
    for (;;) {
        u64 cur = g_cell[s];
        if (cur == ~0ull) return;
        if ((unsigned)(cur >> 16) == key) {
            int ko = (int)(cur & 0xFFFFu);
            int k = ko >> 5, o = ko & 31;
            atomicAdd(&g_cellpts[k*27 + o], 1);
            float* dst = &g_pool[((size_t)(k*27 + o))*LF];
            const float* src = feats + (size_t)i*LF;
            for (int l = 0; l < LF; l++) atomicAdd(&dst[l], src[l]);
        }
        s = (s + 1) & CH_MASK;
    }
}

// ---------------- winners: avg over occupied cells + tiny GEMM ---------------
__global__ void k_cdesc(const float* __restrict__ W, const float* __restrict__ bg) {
    int j = blockIdx.x;
    int t = threadIdx.x;  // 96
    __shared__ float pool[LF];
    if (j == 0) {
        if (t < DF) g_cdesc[t] = bg[t];
        return;
    }
    int k = j - 1;
    if (g_widx[k] < 0) {
        if (t < DF) g_cdesc[j*DF + t] = 0.0f;
        return;
    }
    float acc = 0.0f;
    int m = 0;
    #pragma unroll
    for (int o = 0; o < 27; o++) {
        int c = g_cellpts[k*27 + o];
        if (c > 0) { acc += g_pool[((size_t)(k*27 + o))*LF + t] / (float)c; m++; }
    }
    pool[t] = acc / (float)m;
    __syncthreads();
    if (t < DF) {
        float sacc = 0.0f;
        #pragma unroll 8
        for (int l = 0; l < LF; l++) sacc += pool[l] * W[l*DF + t];
        g_cdesc[j*DF + t] = fmaxf(sacc, 0.0f) * g_wconf[k];
    }
}

// ---------------- hidden: H = relu(F @ W) (overlapped with peak chain) -------
__global__ void k_hidden(const float* __restrict__ feats, const float* __restrict__ W, int N) {
    __shared__ float sW[LF*DF];
    int tid = threadIdx.x;
    for (int i = tid; i < LF*DF; i += BPTS) sW[i] = W[i];
    __syncthreads();
    int i = blockIdx.x * BPTS + tid;
    if (i >= N) return;
    u64 h2r[16];
    #pragma unroll
    for (int d2 = 0; d2 < 16; d2++) h2r[d2] = 0ull;
    const float4* f4 = (const float4*)(feats + (size_t)i * LF);
    #pragma unroll 4
    for (int l4 = 0; l4 < LF/4; l4++) {
        float4 f = f4[l4];
        float fs[4] = {f.x, f.y, f.z, f.w};
        #pragma unroll
        for (int q = 0; q < 4; q++) {
            u64 fb = pack2(fs[q], fs[q]);
            const ulonglong2* w2 = (const ulonglong2*)&sW[(l4*4+q)*DF];
            #pragma unroll
            for (int p = 0; p < 8; p++) {
                ulonglong2 wv = w2[p];
                h2r[p*2+0] = fma2(fb, wv.x, h2r[p*2+0]);
                h2r[p*2+1] = fma2(fb, wv.y, h2r[p*2+1]);
            }
        }
    }
    ulonglong2* out2 = (ulonglong2*)&g_H[(size_t)i*DF];
    #pragma unroll
    for (int p = 0; p < 8; p++) {
        float a, b, c, d;
        unpack2(h2r[p*2+0], a, b); unpack2(h2r[p*2+1], c, d);
        ulonglong2 v;
        v.x = pack2(fmaxf(a, 0.0f), fmaxf(b, 0.0f));
        v.y = pack2(fmaxf(c, 0.0f), fmaxf(d, 0.0f));
        out2[p] = v;
    }
}

// ---------------- inst = H @ cdesc^T -----------------------------------------
#define SMEM_SC   (129*36)
#define SMEM_SO   (BPTS*33)
#define SMEM_INST ((SMEM_SC + SMEM_SO) * (int)sizeof(float))

__global__ void k_inst(float* __restrict__ inst, int N) {
    extern __shared__ float sm[];
    float* sC = sm;
    float* sO = sm + SMEM_SC;
    int tid = threadIdx.x;
    for (int i = tid; i < 129*36; i += BPTS) {
        int j = i / 36, d = i % 36;
        sC[i] = (d < DF) ? g_cdesc[j*DF + d] : 0.0f;
    }
    __syncthreads();

    int p0 = blockIdx.x * BPTS;
    int i = p0 + tid;
    u64 h2r[16];
    if (i < N) {
        const ulonglong2* in2 = (const ulonglong2*)&g_H[(size_t)i*DF];
        #pragma unroll
        for (int p = 0; p < 8; p++) {
            ulonglong2 v = in2[p];
            h2r[p*2+0] = v.x; h2r[p*2+1] = v.y;
        }
    }

    int np = N - p0; if (np > BPTS) np = BPTS;

    for (int jc = 0; jc < 128; jc += 32) {
        if (i < N) {
            #pragma unroll 4
            for (int jj = 0; jj < 32; jj++) {
                const ulonglong2* c2 = (const ulonglong2*)&sC[(jc+jj)*36];
                u64 acc = 0ull;
                #pragma unroll
                for (int p = 0; p < 8; p++) {
                    ulonglong2 cv = c2[p];
                    acc = fma2(h2r[p*2+0], cv.x, acc);
                    acc = fma2(h2r[p*2+1], cv.y, acc);
                }
                float lo, hi; unpack2(acc, lo, hi);
                sO[tid*33 + jj] = lo + hi;
            }
        }
        __syncthreads();
        for (int e = tid; e < np*32; e += BPTS) {
            int p = e >> 5, j0 = e & 31;
            inst[(size_t)(p0 + p) * 129 + jc + j0] = sO[p*33 + j0];
        }
        __syncthreads();
    }
    if (i < N) {
        const ulonglong2* c2 = (const ulonglong2*)&sC[128*36];
        u64 acc = 0ull;
        #pragma unroll
        for (int p = 0; p < 8; p++) {
            ulonglong2 cv = c2[p];
            acc = fma2(h2r[p*2+0], cv.x, acc);
            acc = fma2(h2r[p*2+1], cv.y, acc);
        }
        float lo, hi; unpack2(acc, lo, hi);
        inst[(size_t)i*129 + 128] = lo + hi;
    }
}

// ---------------- launch ------------------------------------------------------
extern "C" void kernel_launch(void* const* d_in, const int* in_sizes, int n_in,
                              void* d_out, int out_size) {
    const int*   coords = (const int*)d_in[0];
    const float* feats  = (const float*)d_in[1];
    const float* scores = (const float*)d_in[2];
    const float* offs   = (const float*)d_in[3];
    const float* W      = (const float*)d_in[4];
    const float* bg     = (const float*)d_in[5];
    int N = in_sizes[0] / 4;
    float* out = (float*)d_out;
    size_t base = (size_t)out_size - (size_t)N * 129;
    float* inst = out + base;

    static cudaStream_t s2 = nullptr;
    static cudaEvent_t evFork = nullptr, evHidden = nullptr;
    if (s2 == nullptr) {
        cudaStreamCreateWithFlags(&s2, cudaStreamNonBlocking);
        cudaEventCreateWithFlags(&evFork, cudaEventDisableTiming);
        cudaEventCreateWithFlags(&evHidden, cudaEventDisableTiming);
        cudaFuncSetAttribute(k_inst, cudaFuncAttributeMaxDynamicSharedMemorySize, SMEM_INST);
    }

    int nb = (N + 255) / 256;

    // fork: hidden GEMM runs concurrently with the peak/cluster chain
    cudaEventRecord(evFork, 0);
    cudaStreamWaitEvent(s2, evFork, 0);
    k_hidden<<<nb, 256, 0, s2>>>(feats, W, N);
    cudaEventRecord(evHidden, s2);

    // peak / cluster chain on the main stream
    k_init<<<2048, 256>>>();
    k_h2_insert<<<nb, 256>>>(coords, scores, N);
    k_h2_score<<<2048, 256>>>(scores);
    k_peaks<<<nb, 256>>>(coords, scores, N);
    k_thresh<<<1, 1024>>>();
    k_collect<<<nb, 256>>>(N);
    k_select<<<1, 1024>>>(out, coords, offs);
    k_match<<<nb, 256>>>(coords, offs, feats, N);
    k_cdesc<<<129, 96>>>(W, bg);

    if (base > 128) cudaMemsetAsync(out + 128, 0, (base - 128) * 4);

    // join: inst needs cdesc (main stream) + hidden (s2)
    cudaStreamWaitEvent(0, evHidden, 0);
    k_inst<<<nb, 256, SMEM_INST>>>(inst, N);
}

// round 15
// speedup vs baseline: 1.2379x; 1.2379x over previous
#include <cuda_runtime.h>
#include <cstdint>
#include <cstddef>

#define MAXN      262144
#define HBITS     19
#define HSIZE     (1u<<HBITS)
#define HMASK     (HSIZE-1u)
#define CH_BITS   14
#define CH_SIZE   (1u<<CH_BITS)
#define CH_MASK   (CH_SIZE-1u)
#define HIST_SIZE 262144
#define CAND_CAP  4096
#define LF        96
#define DF        32
#define TOPK      128
#define BPTS      256
#define GDIM      402
#define BMP_BITS  (GDIM*GDIM*GDIM)            // 64,964,808
#define BMP_WORDS ((BMP_BITS + 31) / 32)      // 2,030,151

typedef unsigned long long u64;

// ---------------- static scratch ---------------------------------------------
__device__ u64      g_h2[HSIZE];       // (cellkey<<18)|minIndex ; ~0 = empty
__device__ unsigned g_bmp[BMP_WORDS];  // occupied-cell bitmap (batch-blind grid)
__device__ u64      g_cell[CH_SIZE];   // (cellkey<<16)|(k<<5)|o ; ~0 = empty
__device__ u64      g_comp[MAXN];      // peak composite keys (0 = not peak)
__device__ int      g_hist[HIST_SIZE];
__device__ u64      g_cand[CAND_CAP];
__device__ int      g_cnt3[4];
__device__ int      g_widx[TOPK];
__device__ float    g_wconf[TOPK];
__device__ float    g_pool[(size_t)TOPK*27*LF];
__device__ int      g_cellpts[TOPK*27];
__device__ float    g_cdesc[129*DF];
__device__ float    g_H[(size_t)MAXN*DF];

// batch-blind key (reference int32 overflow kills the batch term)
__device__ __forceinline__ u64 enc3(int x, int y, int z) {
    return ((u64)(unsigned)(x + 512) << 22) | ((u64)(unsigned)(y + 512) << 11)
         |  (u64)(unsigned)(z + 512);
}
__device__ __forceinline__ unsigned hashk(u64 k) {
    return (unsigned)((k * 0x9E3779B97F4A7C15ull) >> (64 - HBITS));
}
__device__ __forceinline__ unsigned hash14(u64 k) {
    return (unsigned)((k * 0x9E3779B97F4A7C15ull) >> (64 - CH_BITS));
}
// linear cell id for the bitmap; taps span [-1,400] per axis
__device__ __forceinline__ int cellid(int x, int y, int z) {
    return ((x + 1) * GDIM + (y + 1)) * GDIM + (z + 1);
}

__device__ __forceinline__ u64 pack2(float lo, float hi) {
    u64 r; asm("mov.b64 %0, {%1, %2};" : "=l"(r) : "f"(lo), "f"(hi)); return r;
}
__device__ __forceinline__ void unpack2(u64 v, float& lo, float& hi) {
    asm("mov.b64 {%0, %1}, %2;" : "=f"(lo), "=f"(hi) : "l"(v));
}
__device__ __forceinline__ u64 fma2(u64 a, u64 b, u64 c) {
    u64 r; asm("fma.rn.f32x2 %0, %1, %2, %3;" : "=l"(r) : "l"(a), "l"(b), "l"(c)); return r;
}

// ---------------- fused init --------------------------------------------------
__global__ void k_init() {
    int i = blockIdx.x * blockDim.x + threadIdx.x;           // 524288 threads
    if (i < (int)HSIZE)      g_h2[i] = ~0ull;
    if (i < (int)CH_SIZE)    g_cell[i] = ~0ull;
    if (i < HIST_SIZE)       g_hist[i] = 0;
    if (i < TOPK*27)         g_cellpts[i] = 0;
    if (i < TOPK*27*LF)      g_pool[i] = 0.0f;
    if (i < 4)               g_cnt3[i] = 0;
    #pragma unroll
    for (int r = 0; r < 4; r++) {
        int w = i + r * 524288;
        if (w < BMP_WORDS) g_bmp[w] = 0u;
    }
}

// ---------------- h2 insert: per-cell min index + bitmap ---------------------
__global__ void k_h2_insert(const int* __restrict__ coords, const float* __restrict__ scores, int N) {
    int i = blockIdx.x * blockDim.x + threadIdx.x;
    if (i >= N) return;
    if (!(scores[i] > 0.1f)) return;
    int4 c = ((const int4*)coords)[i];
    int cid = cellid(c.y, c.z, c.w);
    atomicOr(&g_bmp[cid >> 5], 1u << (cid & 31));
    u64 key = enc3(c.y, c.z, c.w);
    u64 w = (key << 18) | (unsigned)i;
    unsigned s = hashk(key);
    for (;;) {
        u64 cur = g_h2[s];
        if (cur == ~0ull) {
            u64 old = atomicCAS(&g_h2[s], ~0ull, w);
            if (old == ~0ull) return;
            cur = old;
        }
        if ((cur >> 18) == key) { atomicMin(&g_h2[s], w); return; }
        s = (s + 1) & HMASK;
    }
}

// ---------------- peaks: bitmap-gated 27-tap max -----------------------------
__global__ void k_peaks(const int* __restrict__ coords, const float* __restrict__ scores, int N) {
    int i = blockIdx.x * blockDim.x + threadIdx.x;
    if (i >= N) return;
    float sc = scores[i];
    if (!(sc > 0.1f)) { g_comp[i] = 0ull; return; }
    int4 c = ((const int4*)coords)[i];
    float hmax = -1.0f;
    #pragma unroll
    for (int dx = -1; dx <= 1; dx++)
    #pragma unroll
    for (int dy = -1; dy <= 1; dy++) {
        int base = cellid(c.y + dx, c.z + dy, c.w);      // dz = 0
        int wlo_i = (base - 1) >> 5, whi_i = (base + 1) >> 5;
        unsigned wlo = g_bmp[wlo_i];
        unsigned whi = (whi_i == wlo_i) ? wlo : g_bmp[whi_i];
        #pragma unroll
        for (int dz = -1; dz <= 1; dz++) {
            int cid = base + dz;
            unsigned word = ((cid >> 5) == wlo_i) ? wlo : whi;
            if ((word >> (cid & 31)) & 1u) {
                u64 key = enc3(c.y + dx, c.z + dy, c.w + dz);
                unsigned s = hashk(key);
                for (;;) {
                    u64 cur = g_h2[s];
                    if (cur == ~0ull) break;             // defensive; bit implies present
                    if ((cur >> 18) == key) {
                        hmax = fmaxf(hmax, scores[(int)(cur & 0x3FFFFu)]);
                        break;
                    }
                    s = (s + 1) & HMASK;
                }
            }
        }
    }
    if (hmax == sc) {
        unsigned sb = __float_as_uint(sc);
        g_comp[i] = ((u64)sb << 32) | (u64)(0xFFFFFFFFu - (unsigned)i);
        atomicAdd(&g_hist[sb >> 12], 1);
    } else {
        g_comp[i] = 0ull;
    }
}

// scores < 1.0 => max useful bucket 260095 => first chunk base:
#define THRESH_BASE0 ((260095/1024)*1024)

__global__ void k_thresh() {
    __shared__ int ssum[1024];
    __shared__ int cumsh;
    int t = threadIdx.x;
    if (t == 0) cumsh = 0;
    __syncthreads();
    for (int base = THRESH_BASE0; base >= 0; base -= 1024) {
        ssum[t] = g_hist[base + t];
        __syncthreads();
        for (int o = 512; o > 0; o >>= 1) { if (t < o) ssum[t] += ssum[t + o]; __syncthreads(); }
        int chunk = ssum[0];
        int cum0 = cumsh;
        __syncthreads();
        if (cum0 + chunk >= TOPK) {
            if (t == 0) {
                int cum = cum0;
                for (int i2 = 1023; i2 >= 0; i2--) {
                    cum += g_hist[base + i2];
                    if (cum >= TOPK) { g_cnt3[2] = base + i2; break; }
                }
            }
            return;
        }
        if (t == 0) cumsh = cum0 + chunk;
        __syncthreads();
    }
}

__global__ void k_collect(int N) {
    int i = blockIdx.x * blockDim.x + threadIdx.x;
    if (i >= N) return;
    u64 c = g_comp[i];
    if (c == 0ull) return;
    if ((int)(c >> 44) >= g_cnt3[2]) {
        int p = atomicAdd(&g_cnt3[1], 1);
        if (p < CAND_CAP) g_cand[p] = c;
    }
}

// bitonic sort (desc), emit top-128 + conf, then build winner-cell hash
__global__ void k_select(float* __restrict__ conf_out,
                         const int* __restrict__ coords, const float* __restrict__ offs) {
    __shared__ u64 s[CAND_CAP];
    int t = threadIdx.x; // 1024
    int n = g_cnt3[1]; if (n > CAND_CAP) n = CAND_CAP;
    int M = TOPK; while (M < n) M <<= 1;
    for (int i = t; i < M; i += 1024) s[i] = (i < n) ? g_cand[i] : 0ull;
    __syncthreads();
    for (int k = 2; k <= M; k <<= 1) {
        for (int j = k >> 1; j > 0; j >>= 1) {
            for (int i = t; i < M; i += 1024) {
                int l = i ^ j;
                if (l > i) {
                    u64 a = s[i], b = s[l];
                    bool up = ((i & k) == 0);
                    if (up ? (a < b) : (a > b)) { s[i] = b; s[l] = a; }
                }
            }
            __syncthreads();
        }
    }
    if (t < TOPK) {
        u64 c = s[t];
        int widx = -1;
        if (c != 0ull) {
            float sc = __uint_as_float((unsigned)(c >> 32));
            g_wconf[t] = sc;
            widx = (int)(0xFFFFFFFFu - (unsigned)(c & 0xFFFFFFFFull));
            g_widx[t] = widx;
            conf_out[t] = sc;
        } else {
            g_wconf[t] = 0.0f; g_widx[t] = -1; conf_out[t] = 0.0f;
        }
        if (widx >= 0) {
            int cx = coords[4*widx+1] + (int)offs[3*widx];
            int cy = coords[4*widx+2] + (int)offs[3*widx+1];
            int cz = coords[4*widx+3] + (int)offs[3*widx+2];
            for (int o = 0; o < 27; o++) {
                int dx = o/9 - 1, dy = (o/3)%3 - 1, dz = o%3 - 1;
                u64 key = enc3(cx+dx, cy+dy, cz+dz);
                u64 w = (key << 16) | (unsigned)((t << 5) | o);
                unsigned h = hash14(key);
                for (;;) {
                    u64 old = atomicCAS(&g_cell[h], ~0ull, w);
                    if (old == ~0ull) break;
                    h = (h + 1) & CH_MASK;
                }
            }
        }
    }
}

// ---------------- point pass: one hash probe per point -----------------------
__global__ void k_match(const int* __restrict__ coords, const float* __restrict__ offs,
                        const float* __restrict__ feats, int N) {
    int i = blockIdx.x * blockDim.x + threadIdx.x;
    if (i >= N) return;
    int4 c = ((const int4*)coords)[i];
    int nx = c.y + (int)offs[3*i];
    int ny = c.z + (int)offs[3*i+1];
    int nz = c.w + (int)offs[3*i+2];
    u64 key = enc3(nx, ny, nz);
    unsigned s = hash14(key);
    for (;;) {
        u64 cur = g_cell[s];
        if (cur == ~0ull) return;
        if ((cur >> 16) == key) {
            int ko = (int)(cur & 0xFFFFu);
            int k = ko >> 5, o = ko & 31;
            atomicAdd(&g_cellpts[k*27 + o], 1);
            float* dst = &g_pool[((size_t)(k*27 + o))*LF];
            const float* src = feats + (size_t)i*LF;
            for (int l = 0; l < LF; l++) atomicAdd(&dst[l], src[l]);
        }
        s = (s + 1) & CH_MASK;
    }
}

// ---------------- winners: avg over occupied cells + tiny GEMM ---------------
__global__ void k_cdesc(const float* __restrict__ W, const float* __restrict__ bg) {
    int j = blockIdx.x;
    int t = threadIdx.x;  // 96
    __shared__ float pool[LF];
    if (j == 0) {
        if (t < DF) g_cdesc[t] = bg[t];
        return;
    }
    int k = j - 1;
    if (g_widx[k] < 0) {
        if (t < DF) g_cdesc[j*DF + t] = 0.0f;
        return;
    }
    float acc = 0.0f;
    int m = 0;
    #pragma unroll
    for (int o = 0; o < 27; o++) {
        int c = g_cellpts[k*27 + o];
        if (c > 0) { acc += g_pool[((size_t)(k*27 + o))*LF + t] / (float)c; m++; }
    }
    pool[t] = acc / (float)m;
    __syncthreads();
    if (t < DF) {
        float sacc = 0.0f;
        #pragma unroll 8
        for (int l = 0; l < LF; l++) sacc += pool[l] * W[l*DF + t];
        g_cdesc[j*DF + t] = fmaxf(sacc, 0.0f) * g_wconf[k];
    }
}

// ---------------- hidden: H = relu(F @ W) (overlapped with peak chain) -------
__global__ void k_hidden(const float* __restrict__ feats, const float* __restrict__ W, int N) {
    __shared__ float sW[LF*DF];
    int tid = threadIdx.x;
    for (int i = tid; i < LF*DF; i += BPTS) sW[i] = W[i];
    __syncthreads();
    int i = blockIdx.x * BPTS + tid;
    if (i >= N) return;
    u64 h2r[16];
    #pragma unroll
    for (int d2 = 0; d2 < 16; d2++) h2r[d2] = 0ull;
    const float4* f4 = (const float4*)(feats + (size_t)i * LF);
    #pragma unroll 4
    for (int l4 = 0; l4 < LF/4; l4++) {
        float4 f = f4[l4];
        float fs[4] = {f.x, f.y, f.z, f.w};
        #pragma unroll
        for (int q = 0; q < 4; q++) {
            u64 fb = pack2(fs[q], fs[q]);
            const ulonglong2* w2 = (const ulonglong2*)&sW[(l4*4+q)*DF];
            #pragma unroll
            for (int p = 0; p < 8; p++) {
                ulonglong2 wv = w2[p];
                h2r[p*2+0] = fma2(fb, wv.x, h2r[p*2+0]);
                h2r[p*2+1] = fma2(fb, wv.y, h2r[p*2+1]);
            }
        }
    }
    ulonglong2* out2 = (ulonglong2*)&g_H[(size_t)i*DF];
    #pragma unroll
    for (int p = 0; p < 8; p++) {
        float a, b, c, d;
        unpack2(h2r[p*2+0], a, b); unpack2(h2r[p*2+1], c, d);
        ulonglong2 v;
        v.x = pack2(fmaxf(a, 0.0f), fmaxf(b, 0.0f));
        v.y = pack2(fmaxf(c, 0.0f), fmaxf(d, 0.0f));
        out2[p] = v;
    }
}

// ---------------- inst = H @ cdesc^T -----------------------------------------
#define SMEM_SC   (129*36)
#define SMEM_SO   (BPTS*33)
#define SMEM_INST ((SMEM_SC + SMEM_SO) * (int)sizeof(float))

__global__ void k_inst(float* __restrict__ inst, int N) {
    extern __shared__ float sm[];
    float* sC = sm;
    float* sO = sm + SMEM_SC;
    int tid = threadIdx.x;
    for (int i = tid; i < 129*36; i += BPTS) {
        int j = i / 36, d = i % 36;
        sC[i] = (d < DF) ? g_cdesc[j*DF + d] : 0.0f;
    }
    __syncthreads();

    int p0 = blockIdx.x * BPTS;
    int i = p0 + tid;
    u64 h2r[16];
    if (i < N) {
        const ulonglong2* in2 = (const ulonglong2*)&g_H[(size_t)i*DF];
        #pragma unroll
        for (int p = 0; p < 8; p++) {
            ulonglong2 v = in2[p];
            h2r[p*2+0] = v.x; h2r[p*2+1] = v.y;
        }
    }

    int np = N - p0; if (np > BPTS) np = BPTS;

    for (int jc = 0; jc < 128; jc += 32) {
        if (i < N) {
            #pragma unroll 4
            for (int jj = 0; jj < 32; jj++) {
                const ulonglong2* c2 = (const ulonglong2*)&sC[(jc+jj)*36];
                u64 acc = 0ull;
                #pragma unroll
                for (int p = 0; p < 8; p++) {
                    ulonglong2 cv = c2[p];
                    acc = fma2(h2r[p*2+0], cv.x, acc);
                    acc = fma2(h2r[p*2+1], cv.y, acc);
                }
                float lo, hi; unpack2(acc, lo, hi);
                sO[tid*33 + jj] = lo + hi;
            }
        }
        __syncthreads();
        for (int e = tid; e < np*32; e += BPTS) {
            int p = e >> 5, j0 = e & 31;
            inst[(size_t)(p0 + p) * 129 + jc + j0] = sO[p*33 + j0];
        }
        __syncthreads();
    }
    if (i < N) {
        const ulonglong2* c2 = (const ulonglong2*)&sC[128*36];
        u64 acc = 0ull;
        #pragma unroll
        for (int p = 0; p < 8; p++) {
            ulonglong2 cv = c2[p];
            acc = fma2(h2r[p*2+0], cv.x, acc);
            acc = fma2(h2r[p*2+1], cv.y, acc);
        }
        float lo, hi; unpack2(acc, lo, hi);
        inst[(size_t)i*129 + 128] = lo + hi;
    }
}

// ---------------- launch ------------------------------------------------------
extern "C" void kernel_launch(void* const* d_in, const int* in_sizes, int n_in,
                              void* d_out, int out_size) {
    const int*   coords = (const int*)d_in[0];
    const float* feats  = (const float*)d_in[1];
    const float* scores = (const float*)d_in[2];
    const float* offs   = (const float*)d_in[3];
    const float* W      = (const float*)d_in[4];
    const float* bg     = (const float*)d_in[5];
    int N = in_sizes[0] / 4;
    float* out = (float*)d_out;
    size_t base = (size_t)out_size - (size_t)N * 129;
    float* inst = out + base;

    static cudaStream_t s2 = nullptr;
    static cudaEvent_t evFork = nullptr, evHidden = nullptr;
    if (s2 == nullptr) {
        cudaStreamCreateWithFlags(&s2, cudaStreamNonBlocking);
        cudaEventCreateWithFlags(&evFork, cudaEventDisableTiming);
        cudaEventCreateWithFlags(&evHidden, cudaEventDisableTiming);
        cudaFuncSetAttribute(k_inst, cudaFuncAttributeMaxDynamicSharedMemorySize, SMEM_INST);
    }

    int nb = (N + 255) / 256;

    // fork: hidden GEMM runs concurrently with the peak/cluster chain
    cudaEventRecord(evFork, 0);
    cudaStreamWaitEvent(s2, evFork, 0);
    k_hidden<<<nb, 256, 0, s2>>>(feats, W, N);
    cudaEventRecord(evHidden, s2);

    // peak / cluster chain on the main stream
    k_init<<<2048, 256>>>();
    k_h2_insert<<<nb, 256>>>(coords, scores, N);
    k_peaks<<<nb, 256>>>(coords, scores, N);
    k_thresh<<<1, 1024>>>();
    k_collect<<<nb, 256>>>(N);
    k_select<<<1, 1024>>>(out, coords, offs);
    k_match<<<nb, 256>>>(coords, offs, feats, N);
    k_cdesc<<<129, 96>>>(W, bg);

    if (base > 128) cudaMemsetAsync(out + 128, 0, (base - 128) * 4);

    // join: inst needs cdesc (main stream) + hidden (s2)
    cudaStreamWaitEvent(0, evHidden, 0);
    k_inst<<<nb, 256, SMEM_INST>>>(inst, N);
}